// round 6
// baseline (speedup 1.0000x reference)
#include <cuda_runtime.h>
#include <cstdint>

// 3x3 conv, stride 1, pad 1, NCHW fp32. B=8, CIN=COUT=16, H=W=1024.
// Block: 16 rows x 64 cols spatial tile, all 16 cout.
// 256 threads = 2 cout-groups (8 cout each) x 128 positions (16 rows x 8 xgroups, VEC=8).
// All 16 cin staged in SMEM with bank-conflict-free swizzle; weights duplicated
// as (w,w) float2 so LDS.64 broadcast feeds fma.rn.f32x2 directly.

#define CIN   16
#define COUT  16
#define Hh    1024
#define Ww    1024
#define Bb    8

#define TH    16          // output rows per block
#define TW    64          // output cols per block
#define VEC   8           // pixels per thread
#define NCO   8           // couts per thread group
#define THREADS 256

#define IN_ROWS  (TH + 2)         // 18
#define IN_COLS  (TW + 2)         // 66 logical cols (lc 0..65)
#define PITCH    74               // >= 68 (max swizzled col 67+1), and PITCH % 8 == 2
#define SIN_FLOATS (CIN * IN_ROWS * PITCH)          // 16*18*74 = 21312
#define SW_FLOAT2  (CIN * COUT * 9)                 // 2304
#define SMEM_BYTES (SIN_FLOATS * 4 + SW_FLOAT2 * 8) // 85248 + 18432 = 103680

typedef unsigned long long ull;

__device__ __forceinline__ void fma2(ull& d, ull a, ull b) {
    asm("fma.rn.f32x2 %0, %1, %2, %3;" : "=l"(d) : "l"(a), "l"(b), "l"(d));
}
__device__ __forceinline__ ull pack2(float lo, float hi) {
    ull r;
    asm("mov.b64 %0, {%1, %2};" : "=l"(r) : "f"(lo), "f"(hi));
    return r;
}
__device__ __forceinline__ void unpack2(ull v, float& lo, float& hi) {
    asm("mov.b64 {%0, %1}, %2;" : "=f"(lo), "=f"(hi) : "l"(v));
}

// swizzled column: lc in [0,65] -> pc = lc + (lc>>5), spreads stride-8 lane
// patterns over distinct banks; PITCH % 8 == 2 keeps the 4 warp-rows disjoint.
__device__ __forceinline__ int swz(int lc) { return lc + (lc >> 5); }

__global__ __launch_bounds__(THREADS, 2)
void conv3x3_kernel(const float* __restrict__ x,
                    const float* __restrict__ w,
                    float* __restrict__ out)
{
    extern __shared__ float smem[];
    float* s_in = smem;                                  // [ci][row][PITCH]
    float2* s_w = (float2*)(smem + SIN_FLOATS);          // [ci][co][9] duplicated

    const int t  = threadIdx.x;
    const int bx = blockIdx.x;       // 0..15  -> x_base
    const int by = blockIdx.y;       // 0..63  -> y_base
    const int b  = blockIdx.z;       // batch
    const int x_base = bx * TW;
    const int y_base = by * TH;

    // ---- stage weights: s_w[ci][co][k] = (W[co][ci][k], W[co][ci][k]) ----
    for (int i = t; i < SW_FLOAT2; i += THREADS) {
        int ci = i / (COUT * 9);
        int r  = i - ci * (COUT * 9);
        int co = r / 9;
        int k  = r - co * 9;
        float wv = w[((co * CIN + ci) * 9) + k];
        s_w[(ci * COUT + co) * 9 + k] = make_float2(wv, wv);
    }

    // ---- stage input: 16 ci x 18 rows x 66 cols, zero-padded halo ----
    const int TOT = CIN * IN_ROWS * IN_COLS;             // 19008
    for (int i = t; i < TOT; i += THREADS) {
        int ci  = i / (IN_ROWS * IN_COLS);
        int rem = i - ci * (IN_ROWS * IN_COLS);
        int r   = rem / IN_COLS;
        int lc  = rem - r * IN_COLS;
        int gy  = y_base + r - 1;
        int gx  = x_base + lc - 1;
        float v = 0.0f;
        if ((unsigned)gy < (unsigned)Hh && (unsigned)gx < (unsigned)Ww)
            v = x[(((size_t)b * CIN + ci) * Hh + gy) * Ww + gx];
        s_in[(ci * IN_ROWS + r) * PITCH + swz(lc)] = v;
    }
    __syncthreads();

    // ---- thread mapping ----
    const int grp = t >> 7;          // 0/1 -> cout half
    const int p   = t & 127;
    const int ty  = p >> 3;          // 0..15 output row in tile
    const int xg  = p & 7;           // 0..7 x-group
    const int x0  = xg * VEC;        // tile-local first pixel
    const int co0 = grp * NCO;

    ull acc[NCO][4];
    #pragma unroll
    for (int c = 0; c < NCO; c++)
        #pragma unroll
        for (int q = 0; q < 4; q++) acc[c][q] = 0ull;

    #pragma unroll 1
    for (int ci = 0; ci < CIN; ci++) {
        const float* in_ci = &s_in[ci * IN_ROWS * PITCH];
        const float2* w_ci = &s_w[(ci * COUT + co0) * 9];
        #pragma unroll
        for (int ry = 0; ry < 3; ry++) {
            const float* row = &in_ci[(ty + ry) * PITCH];
            float v[VEC + 2];
            #pragma unroll
            for (int j = 0; j < VEC + 2; j++)
                v[j] = row[swz(x0 + j)];
            ull pr[VEC + 1];
            #pragma unroll
            for (int j = 0; j < VEC + 1; j++)
                pr[j] = pack2(v[j], v[j + 1]);
            #pragma unroll
            for (int c = 0; c < NCO; c++) {
                const ull* wp = (const ull*)&w_ci[c * 9 + ry * 3];
                #pragma unroll
                for (int kx = 0; kx < 3; kx++) {
                    ull w2 = wp[kx];
                    #pragma unroll
                    for (int q = 0; q < 4; q++)
                        fma2(acc[c][q], pr[kx + 2 * q], w2);
                }
            }
        }
    }

    // ---- write back: float4 stores, 8 lanes x 16B contiguous ----
    const int oy = y_base + ty;
    const int ox = x_base + x0;
    #pragma unroll
    for (int c = 0; c < NCO; c++) {
        float* op = &out[(((size_t)b * COUT + (co0 + c)) * Hh + oy) * Ww + ox];
        float r0, r1, r2, r3, r4, r5, r6, r7;
        unpack2(acc[c][0], r0, r1);
        unpack2(acc[c][1], r2, r3);
        unpack2(acc[c][2], r4, r5);
        unpack2(acc[c][3], r6, r7);
        ((float4*)op)[0] = make_float4(r0, r1, r2, r3);
        ((float4*)op)[1] = make_float4(r4, r5, r6, r7);
    }
}

extern "C" void kernel_launch(void* const* d_in, const int* in_sizes, int n_in,
                              void* d_out, int out_size)
{
    const float* x = (const float*)d_in[0];
    const float* w = (const float*)d_in[1];
    float* out = (float*)d_out;

    // Unconditional (idempotent, not stream-ordered, graph-capture safe) —
    // no static guard, per harness determinism rules.
    cudaFuncSetAttribute(conv3x3_kernel,
                         cudaFuncAttributeMaxDynamicSharedMemorySize,
                         SMEM_BYTES);

    dim3 grid(Ww / TW, Hh / TH, Bb);   // (16, 64, 8)
    conv3x3_kernel<<<grid, THREADS, SMEM_BYTES>>>(x, w, out);
}